// round 2
// baseline (speedup 1.0000x reference)
#include <cuda_runtime.h>
#include <cuda_bf16.h>

// Problem constants (fixed by the reference).
#define N_NODES_MAX 50000
#define N_EDGES_MAX 1250000
#define D 64

// ---------------- scratch (device globals; no allocations allowed) ----------
__device__ int   g_deg[N_NODES_MAX + 1];
__device__ int   g_cur[N_NODES_MAX + 1];
__device__ int   g_off[N_NODES_MAX + 2];
__device__ int   g_ssrc[N_EDGES_MAX];
__device__ float g_Xp[(size_t)N_NODES_MAX * D];   // X' = feature @ W^T

// ---------------- 0) zero counters ------------------------------------------
__global__ void zero_kernel(int n) {
    int i = blockIdx.x * blockDim.x + threadIdx.x;
    if (i < n) { g_deg[i] = 0; g_cur[i] = 0; }
}

// ---------------- 1) degree histogram over dst -------------------------------
__global__ void hist_kernel(const int* __restrict__ dst, int n_edges) {
    int e = blockIdx.x * blockDim.x + threadIdx.x;
    if (e < n_edges) atomicAdd(&g_deg[dst[e]], 1);
}

// ---------------- 2) exclusive scan (single block, 1024 threads) -------------
__global__ void scan_kernel(int n) {
    __shared__ int wsum[32];
    __shared__ int carry_s;
    int tid = threadIdx.x, lane = tid & 31, wid = tid >> 5;
    if (tid == 0) carry_s = 0;
    __syncthreads();
    for (int base = 0; base < n; base += 1024) {
        int i = base + tid;
        int v = (i < n) ? g_deg[i] : 0;
        int x = v;
        #pragma unroll
        for (int o = 1; o < 32; o <<= 1) {
            int y = __shfl_up_sync(0xffffffffu, x, o);
            if (lane >= o) x += y;
        }
        if (lane == 31) wsum[wid] = x;
        __syncthreads();
        if (wid == 0) {
            int s = wsum[lane];
            #pragma unroll
            for (int o = 1; o < 32; o <<= 1) {
                int y = __shfl_up_sync(0xffffffffu, s, o);
                if (lane >= o) s += y;
            }
            wsum[lane] = s;  // inclusive scan of per-warp sums
        }
        __syncthreads();
        int prev_warps = (wid == 0) ? 0 : wsum[wid - 1];
        int excl = carry_s + prev_warps + (x - v);
        if (i < n) g_off[i] = excl;
        __syncthreads();
        if (tid == 0) carry_s += wsum[31];
        __syncthreads();
    }
    if (threadIdx.x == 0) g_off[n] = carry_s;
}

// ---------------- 3) bucket fill: sorted_src by dst --------------------------
__global__ void fill_kernel(const int* __restrict__ src, const int* __restrict__ dst,
                            int n_edges) {
    int e = blockIdx.x * blockDim.x + threadIdx.x;
    if (e < n_edges) {
        int d = dst[e];
        int p = g_off[d] + atomicAdd(&g_cur[d], 1);
        g_ssrc[p] = src[e];
    }
}

// ---------------- 4) transform: X' = F @ W^T ---------------------------------
// 256 threads = 4 row-groups of 64. Thread with c = tid%64 owns output col c,
// keeps W[c][0..63] in registers (staged via padded shared, conflict-free).
__global__ void __launch_bounds__(256) transform_kernel(
        const float* __restrict__ F, const float* __restrict__ W,
        int n_nodes) {
    __shared__ float  shW[64 * 68];     // pad row stride to 68 floats
    __shared__ float4 fsh[4][16];       // 4 staged feature rows

    for (int idx = threadIdx.x; idx < 64 * 64; idx += blockDim.x)
        shW[(idx >> 6) * 68 + (idx & 63)] = W[idx];
    __syncthreads();

    int c = threadIdx.x & 63;
    int g = threadIdx.x >> 6;
    float w[64];
    #pragma unroll
    for (int k = 0; k < 16; k++) {
        float4 t = *reinterpret_cast<const float4*>(&shW[c * 68 + 4 * k]);
        w[4 * k] = t.x; w[4 * k + 1] = t.y; w[4 * k + 2] = t.z; w[4 * k + 3] = t.w;
    }
    __syncthreads();

    for (int r0 = blockIdx.x * 4; r0 < n_nodes; r0 += gridDim.x * 4) {
        if (threadIdx.x < 64) {
            int rr = threadIdx.x >> 4, kk = threadIdx.x & 15;
            int r = r0 + rr;
            fsh[rr][kk] = (r < n_nodes)
                ? reinterpret_cast<const float4*>(F)[(size_t)r * 16 + kk]
                : make_float4(0.f, 0.f, 0.f, 0.f);
        }
        __syncthreads();
        int r = r0 + g;
        if (r < n_nodes) {
            float acc = 0.f;
            #pragma unroll
            for (int k = 0; k < 16; k++) {
                float4 f = fsh[g][k];
                acc += f.x * w[4 * k]     + f.y * w[4 * k + 1]
                     + f.z * w[4 * k + 2] + f.w * w[4 * k + 3];
            }
            g_Xp[(size_t)r * 64 + c] = acc;
        }
        __syncthreads();
    }
}

// ---------------- 5) aggregate: one warp per node ----------------------------
// Each lane owns a float2 (2 columns). Gather X'[s] rows (coalesced 256B),
// sum, add bias, write directly to d_out.
__global__ void __launch_bounds__(256) aggregate_kernel(
        const float* __restrict__ bias, float* __restrict__ out, int n_nodes) {
    int w    = (blockIdx.x * blockDim.x + threadIdx.x) >> 5;
    int lane = threadIdx.x & 31;
    if (w >= n_nodes) return;
    int j = g_off[w], e = g_off[w + 1];
    const float2* X2 = reinterpret_cast<const float2*>(g_Xp);
    float ax = 0.f, ay = 0.f;
    for (; j + 4 <= e; j += 4) {
        int s0 = g_ssrc[j], s1 = g_ssrc[j + 1], s2 = g_ssrc[j + 2], s3 = g_ssrc[j + 3];
        float2 v0 = X2[s0 * 32 + lane];
        float2 v1 = X2[s1 * 32 + lane];
        float2 v2 = X2[s2 * 32 + lane];
        float2 v3 = X2[s3 * 32 + lane];
        ax += v0.x + v1.x + v2.x + v3.x;
        ay += v0.y + v1.y + v2.y + v3.y;
    }
    for (; j < e; j++) {
        int s = g_ssrc[j];
        float2 v = X2[s * 32 + lane];
        ax += v.x; ay += v.y;
    }
    float2 bb = reinterpret_cast<const float2*>(bias)[lane];
    float2 o;
    o.x = ax + bb.x;
    o.y = ay + bb.y;
    reinterpret_cast<float2*>(out)[(size_t)w * 32 + lane] = o;
}

// ---------------- launch -----------------------------------------------------
extern "C" void kernel_launch(void* const* d_in, const int* in_sizes, int n_in,
                              void* d_out, int out_size) {
    const float* feature = (const float*)d_in[0];
    const int*   src     = (const int*)d_in[1];
    const int*   dst     = (const int*)d_in[2];
    const float* W       = (const float*)d_in[3];
    const float* b       = (const float*)d_in[4];
    float*       out     = (float*)d_out;

    int n_nodes = in_sizes[0] / D;     // 50000
    int n_edges = in_sizes[1];         // 1250000

    zero_kernel<<<(n_nodes + 255) / 256, 256>>>(n_nodes);
    hist_kernel<<<(n_edges + 255) / 256, 256>>>(dst, n_edges);
    transform_kernel<<<1184, 256>>>(feature, W, n_nodes);   // independent of CSR build
    scan_kernel<<<1, 1024>>>(n_nodes);
    fill_kernel<<<(n_edges + 255) / 256, 256>>>(src, dst, n_edges);
    aggregate_kernel<<<(n_nodes * 32 + 255) / 256, 256>>>(b, out, n_nodes);
}

// round 3
// speedup vs baseline: 1.3059x; 1.3059x over previous
#include <cuda_runtime.h>
#include <cuda_bf16.h>

#define N_NODES_MAX 50000
#define N_EDGES_MAX 1250000
#define D 64

// ---------------- scratch (device globals; zero-initialized at load) --------
// INVARIANT: g_deg is all-zero at kernel_launch entry. hist builds degrees,
// fill consumes them back to exactly zero via atomicAdd(-1), so every replay
// re-establishes the invariant. No zeroing kernel needed.
__device__ int   g_deg[N_NODES_MAX + 8];
__device__ int   g_off[N_NODES_MAX + 1032];      // per-block-local exclusive scan
__device__ int   g_bsum[1024];                   // scanned block sums
__device__ int   g_ssrc[N_EDGES_MAX];
__device__ float g_Xp[(size_t)N_NODES_MAX * D];  // X' = feature @ W^T

// ---------------- 1) fused: histogram(dst) | transform X'=F@W^T -------------
// Block roles interleaved (every 5th block transforms) so both independent
// workloads overlap across the chip instead of serializing in the stream.
__global__ void __launch_bounds__(256) ht_kernel(
        const float* __restrict__ F, const float* __restrict__ W,
        const int* __restrict__ dst, int n_nodes, int n_edges) {
    __shared__ float  shW[64 * 68];
    __shared__ float4 fsh[4][16];

    int bid = blockIdx.x;
    int nT  = (gridDim.x + 4) / 5;           // transform block count
    int nH  = gridDim.x - nT;                // hist block count

    if (bid % 5 == 0) {
        // ----- transform role: 4 rows per tile, col-per-thread, W in regs ---
        int tb = bid / 5;
        for (int idx = threadIdx.x; idx < 64 * 64; idx += 256)
            shW[(idx >> 6) * 68 + (idx & 63)] = W[idx];
        __syncthreads();

        int c = threadIdx.x & 63;
        int g = threadIdx.x >> 6;
        float w[64];
        #pragma unroll
        for (int k = 0; k < 16; k++) {
            float4 t = *reinterpret_cast<const float4*>(&shW[c * 68 + 4 * k]);
            w[4*k] = t.x; w[4*k+1] = t.y; w[4*k+2] = t.z; w[4*k+3] = t.w;
        }
        __syncthreads();

        for (int r0 = tb * 4; r0 < n_nodes; r0 += nT * 4) {
            if (threadIdx.x < 64) {
                int rr = threadIdx.x >> 4, kk = threadIdx.x & 15;
                int r = r0 + rr;
                fsh[rr][kk] = (r < n_nodes)
                    ? reinterpret_cast<const float4*>(F)[(size_t)r * 16 + kk]
                    : make_float4(0.f, 0.f, 0.f, 0.f);
            }
            __syncthreads();
            int r = r0 + g;
            if (r < n_nodes) {
                float acc = 0.f;
                #pragma unroll
                for (int k = 0; k < 16; k++) {
                    float4 f = fsh[g][k];
                    acc += f.x * w[4*k]   + f.y * w[4*k+1]
                         + f.z * w[4*k+2] + f.w * w[4*k+3];
                }
                g_Xp[(size_t)r * 64 + c] = acc;
            }
            __syncthreads();
        }
    } else {
        // ----- hist role: degree histogram over dst -------------------------
        int hb = bid - bid / 5 - 1;
        for (int e = hb * 256 + threadIdx.x; e < n_edges; e += nH * 256)
            atomicAdd(&g_deg[dst[e]], 1);
    }
}

// ---------------- 2a) per-block local exclusive scan of g_deg ---------------
__global__ void __launch_bounds__(1024) scan1_kernel(int n) {
    __shared__ int wsum[32];
    int i = blockIdx.x * 1024 + threadIdx.x;
    int lane = threadIdx.x & 31, wid = threadIdx.x >> 5;
    int v = (i < n) ? g_deg[i] : 0;
    int x = v;
    #pragma unroll
    for (int o = 1; o < 32; o <<= 1) {
        int y = __shfl_up_sync(0xffffffffu, x, o);
        if (lane >= o) x += y;
    }
    if (lane == 31) wsum[wid] = x;
    __syncthreads();
    if (wid == 0) {
        int s = wsum[lane];
        #pragma unroll
        for (int o = 1; o < 32; o <<= 1) {
            int y = __shfl_up_sync(0xffffffffu, s, o);
            if (lane >= o) s += y;
        }
        wsum[lane] = s;
    }
    __syncthreads();
    int excl = ((wid == 0) ? 0 : wsum[wid - 1]) + (x - v);
    if (i <= n) g_off[i] = excl;                   // local (pre-bsum) offsets
    if (threadIdx.x == 1023) g_bsum[blockIdx.x] = wsum[31];  // block total
}

// ---------------- 2b) exclusive scan of the block sums (tiny) ---------------
__global__ void __launch_bounds__(1024) scan2_kernel(int nblk) {
    __shared__ int wsum[32];
    int tid = threadIdx.x, lane = tid & 31, wid = tid >> 5;
    int v = (tid < nblk) ? g_bsum[tid] : 0;
    int x = v;
    #pragma unroll
    for (int o = 1; o < 32; o <<= 1) {
        int y = __shfl_up_sync(0xffffffffu, x, o);
        if (lane >= o) x += y;
    }
    if (lane == 31) wsum[wid] = x;
    __syncthreads();
    if (wid == 0) {
        int s = wsum[lane];
        #pragma unroll
        for (int o = 1; o < 32; o <<= 1) {
            int y = __shfl_up_sync(0xffffffffu, s, o);
            if (lane >= o) s += y;
        }
        wsum[lane] = s;
    }
    __syncthreads();
    int excl = ((wid == 0) ? 0 : wsum[wid - 1]) + (x - v);
    if (tid < nblk) g_bsum[tid] = excl;
}

// ---------------- 3) bucket fill (consumes g_deg back to zero) --------------
__global__ void fill_kernel(const int* __restrict__ src, const int* __restrict__ dst,
                            int n_edges) {
    int e = blockIdx.x * blockDim.x + threadIdx.x;
    if (e < n_edges) {
        int d = dst[e];
        int r = atomicAdd(&g_deg[d], -1);          // claims slot, restores zero
        g_ssrc[g_off[d] + g_bsum[d >> 10] + r - 1] = src[e];
    }
}

// ---------------- 4) aggregate: one warp per node ----------------------------
__global__ void __launch_bounds__(256) aggregate_kernel(
        const float* __restrict__ bias, float* __restrict__ out, int n_nodes) {
    int w    = (blockIdx.x * blockDim.x + threadIdx.x) >> 5;
    int lane = threadIdx.x & 31;
    if (w >= n_nodes) return;
    int j = g_off[w]     + g_bsum[w >> 10];
    int e = g_off[w + 1] + g_bsum[(w + 1) >> 10];
    const float2* X2 = reinterpret_cast<const float2*>(g_Xp);
    float ax = 0.f, ay = 0.f;
    for (; j + 4 <= e; j += 4) {
        int s0 = __ldg(&g_ssrc[j]);
        int s1 = __ldg(&g_ssrc[j + 1]);
        int s2 = __ldg(&g_ssrc[j + 2]);
        int s3 = __ldg(&g_ssrc[j + 3]);
        float2 v0 = __ldg(&X2[s0 * 32 + lane]);
        float2 v1 = __ldg(&X2[s1 * 32 + lane]);
        float2 v2 = __ldg(&X2[s2 * 32 + lane]);
        float2 v3 = __ldg(&X2[s3 * 32 + lane]);
        ax += v0.x + v1.x + v2.x + v3.x;
        ay += v0.y + v1.y + v2.y + v3.y;
    }
    for (; j < e; j++) {
        int s = __ldg(&g_ssrc[j]);
        float2 v = __ldg(&X2[s * 32 + lane]);
        ax += v.x; ay += v.y;
    }
    float2 bb = __ldg(&reinterpret_cast<const float2*>(bias)[lane]);
    float2 o;
    o.x = ax + bb.x;
    o.y = ay + bb.y;
    reinterpret_cast<float2*>(out)[(size_t)w * 32 + lane] = o;
}

// ---------------- launch -----------------------------------------------------
extern "C" void kernel_launch(void* const* d_in, const int* in_sizes, int n_in,
                              void* d_out, int out_size) {
    const float* feature = (const float*)d_in[0];
    const int*   src     = (const int*)d_in[1];
    const int*   dst     = (const int*)d_in[2];
    const float* W       = (const float*)d_in[3];
    const float* b       = (const float*)d_in[4];
    float*       out     = (float*)d_out;

    int n_nodes = in_sizes[0] / D;     // 50000
    int n_edges = in_sizes[1];         // 1250000
    int nblk    = (n_nodes + 1 + 1023) / 1024;   // scan blocks (49)

    ht_kernel<<<6080, 256>>>(feature, W, dst, n_nodes, n_edges);
    scan1_kernel<<<nblk, 1024>>>(n_nodes);
    scan2_kernel<<<1, 1024>>>(nblk);
    fill_kernel<<<(n_edges + 255) / 256, 256>>>(src, dst, n_edges);
    aggregate_kernel<<<(n_nodes * 32 + 255) / 256, 256>>>(b, out, n_nodes);
}